// round 4
// baseline (speedup 1.0000x reference)
#include <cuda_runtime.h>
#include <cuda_bf16.h>
#include <cstdint>

// L1 loss: sum(|out - target|) / N_VEH over N_VEH x N_FEAT fp32.
// Pure HBM-streaming reduction: 536.9 MB read, 4 B written.
// Single kernel launch; last-finishing block does the final reduce
// (self-resetting atomicInc ticket -> graph-replay safe, no memset node).
// NOTE: no min-blocks-per-SM cap — the 32-reg cap in R3 destroyed load MLP
// (8 LDG.128 in flight needs 32 payload regs alone) and cost 5% DRAM BW.

static constexpr int N_FEAT = 8;
static constexpr int BLOCK  = 256;
static constexpr int GRID   = 2048;   // config that measured 6870 GB/s (86.7% DRAM)

__device__ float        g_partials[GRID];
__device__ unsigned int g_ticket = 0;

__global__ __launch_bounds__(BLOCK)
void l1_reduce_kernel(const float4* __restrict__ a,
                      const float4* __restrict__ b,
                      float* __restrict__ res,
                      int n_vec4, float inv_rows)
{
    float acc = 0.0f;
    int stride = GRID * BLOCK;
    int i = blockIdx.x * BLOCK + threadIdx.x;

    // Batch 4 independent float4-pairs per iteration (8 LDG.128 in flight).
    #pragma unroll 1
    for (; i + 3 * stride < n_vec4; i += 4 * stride) {
        float4 a0 = __ldcs(&a[i]);
        float4 a1 = __ldcs(&a[i + stride]);
        float4 a2 = __ldcs(&a[i + 2 * stride]);
        float4 a3 = __ldcs(&a[i + 3 * stride]);
        float4 b0 = __ldcs(&b[i]);
        float4 b1 = __ldcs(&b[i + stride]);
        float4 b2 = __ldcs(&b[i + 2 * stride]);
        float4 b3 = __ldcs(&b[i + 3 * stride]);
        acc += fabsf(a0.x - b0.x) + fabsf(a0.y - b0.y) + fabsf(a0.z - b0.z) + fabsf(a0.w - b0.w);
        acc += fabsf(a1.x - b1.x) + fabsf(a1.y - b1.y) + fabsf(a1.z - b1.z) + fabsf(a1.w - b1.w);
        acc += fabsf(a2.x - b2.x) + fabsf(a2.y - b2.y) + fabsf(a2.z - b2.z) + fabsf(a2.w - b2.w);
        acc += fabsf(a3.x - b3.x) + fabsf(a3.y - b3.y) + fabsf(a3.z - b3.z) + fabsf(a3.w - b3.w);
    }
    // Tail.
    for (; i < n_vec4; i += stride) {
        float4 av = __ldcs(&a[i]);
        float4 bv = __ldcs(&b[i]);
        acc += fabsf(av.x - bv.x) + fabsf(av.y - bv.y) + fabsf(av.z - bv.z) + fabsf(av.w - bv.w);
    }

    // Warp reduce.
    #pragma unroll
    for (int o = 16; o > 0; o >>= 1)
        acc += __shfl_xor_sync(0xFFFFFFFFu, acc, o);

    __shared__ float smem[BLOCK / 32];
    __shared__ bool  is_last;
    if ((threadIdx.x & 31) == 0)
        smem[threadIdx.x >> 5] = acc;
    __syncthreads();

    if (threadIdx.x == 0) {
        float bsum = 0.0f;
        #pragma unroll
        for (int w = 0; w < BLOCK / 32; w++) bsum += smem[w];
        g_partials[blockIdx.x] = bsum;
        __threadfence();
        // atomicInc wraps to 0 when old == GRID-1 -> self-resetting across
        // graph replays; the wrapping thread belongs to the last block.
        unsigned int t = atomicInc(&g_ticket, GRID - 1);
        is_last = (t == GRID - 1);
    }
    __syncthreads();

    if (is_last) {
        __threadfence();  // acquire: observe all blocks' partials
        float s = 0.0f;
        for (int j = threadIdx.x; j < GRID; j += BLOCK)
            s += g_partials[j];
        #pragma unroll
        for (int o = 16; o > 0; o >>= 1)
            s += __shfl_xor_sync(0xFFFFFFFFu, s, o);
        if ((threadIdx.x & 31) == 0)
            smem[threadIdx.x >> 5] = s;
        __syncthreads();
        if (threadIdx.x == 0) {
            float tot = 0.0f;
            #pragma unroll
            for (int w = 0; w < BLOCK / 32; w++) tot += smem[w];
            *res = tot * inv_rows;
        }
    }
}

extern "C" void kernel_launch(void* const* d_in, const int* in_sizes, int n_in,
                              void* d_out, int out_size)
{
    const float4* a = (const float4*)d_in[0];   // out
    const float4* b = (const float4*)d_in[1];   // target
    float* res = (float*)d_out;

    long long n_elem = (long long)in_sizes[0];  // N_VEH * N_FEAT
    int n_vec4 = (int)(n_elem / 4);
    float inv_rows = (float)((double)N_FEAT / (double)n_elem);

    l1_reduce_kernel<<<GRID, BLOCK>>>(a, b, res, n_vec4, inv_rows);
}

// round 5
// speedup vs baseline: 1.0197x; 1.0197x over previous
#include <cuda_runtime.h>
#include <cuda_bf16.h>
#include <cstdint>

// L1 loss: sum(|out - target|) / N_VEH over N_VEH x N_FEAT fp32.
// Pure HBM-streaming reduction: 536.9 MB read, 4 B written.
//
// Structure: R2's streaming loop + parallel per-block atomicAdd epilogue
// (proven 78.7us kernel / 86.7% DRAM), but accumulating into a __device__
// global instead of d_out so NO memset node is needed. A self-resetting
// atomicInc ticket elects the last-finishing block, which publishes the
// scaled result to d_out and zeroes the accumulator for the next graph
// replay. Avoids R4's serial 2048-partial tail entirely.

static constexpr int N_FEAT = 8;
static constexpr int BLOCK  = 256;
static constexpr int GRID   = 2048;

__device__ float        g_accum  = 0.0f;
__device__ unsigned int g_ticket = 0;

__global__ __launch_bounds__(BLOCK)
void l1_reduce_kernel(const float4* __restrict__ a,
                      const float4* __restrict__ b,
                      float* __restrict__ res,
                      int n_vec4, float inv_rows)
{
    float acc = 0.0f;
    int stride = GRID * BLOCK;
    int i = blockIdx.x * BLOCK + threadIdx.x;

    // Batch 4 independent float4-pairs per iteration (8 LDG.128 in flight).
    #pragma unroll 1
    for (; i + 3 * stride < n_vec4; i += 4 * stride) {
        float4 a0 = __ldcs(&a[i]);
        float4 a1 = __ldcs(&a[i + stride]);
        float4 a2 = __ldcs(&a[i + 2 * stride]);
        float4 a3 = __ldcs(&a[i + 3 * stride]);
        float4 b0 = __ldcs(&b[i]);
        float4 b1 = __ldcs(&b[i + stride]);
        float4 b2 = __ldcs(&b[i + 2 * stride]);
        float4 b3 = __ldcs(&b[i + 3 * stride]);
        acc += fabsf(a0.x - b0.x) + fabsf(a0.y - b0.y) + fabsf(a0.z - b0.z) + fabsf(a0.w - b0.w);
        acc += fabsf(a1.x - b1.x) + fabsf(a1.y - b1.y) + fabsf(a1.z - b1.z) + fabsf(a1.w - b1.w);
        acc += fabsf(a2.x - b2.x) + fabsf(a2.y - b2.y) + fabsf(a2.z - b2.z) + fabsf(a2.w - b2.w);
        acc += fabsf(a3.x - b3.x) + fabsf(a3.y - b3.y) + fabsf(a3.z - b3.z) + fabsf(a3.w - b3.w);
    }
    // Tail.
    for (; i < n_vec4; i += stride) {
        float4 av = __ldcs(&a[i]);
        float4 bv = __ldcs(&b[i]);
        acc += fabsf(av.x - bv.x) + fabsf(av.y - bv.y) + fabsf(av.z - bv.z) + fabsf(av.w - bv.w);
    }

    // Warp reduce.
    #pragma unroll
    for (int o = 16; o > 0; o >>= 1)
        acc += __shfl_xor_sync(0xFFFFFFFFu, acc, o);

    __shared__ float smem[BLOCK / 32];
    if ((threadIdx.x & 31) == 0)
        smem[threadIdx.x >> 5] = acc;
    __syncthreads();

    if (threadIdx.x == 0) {
        float bsum = 0.0f;
        #pragma unroll
        for (int w = 0; w < BLOCK / 32; w++) bsum += smem[w];

        atomicAdd(&g_accum, bsum);
        __threadfence();
        // atomicInc wraps to 0 when old == GRID-1 -> self-resetting across
        // graph replays. Every block's atomicAdd precedes its atomicInc, so
        // the wrapping thread observes all contributions.
        unsigned int t = atomicInc(&g_ticket, GRID - 1);
        if (t == GRID - 1) {
            __threadfence();
            float tot = *((volatile float*)&g_accum);
            *res = tot * inv_rows;
            g_accum = 0.0f;   // reset for next graph replay
        }
    }
}

extern "C" void kernel_launch(void* const* d_in, const int* in_sizes, int n_in,
                              void* d_out, int out_size)
{
    const float4* a = (const float4*)d_in[0];   // out
    const float4* b = (const float4*)d_in[1];   // target
    float* res = (float*)d_out;

    long long n_elem = (long long)in_sizes[0];  // N_VEH * N_FEAT
    int n_vec4 = (int)(n_elem / 4);
    float inv_rows = (float)((double)N_FEAT / (double)n_elem);

    l1_reduce_kernel<<<GRID, BLOCK>>>(a, b, res, n_vec4, inv_rows);
}

// round 6
// speedup vs baseline: 1.0246x; 1.0048x over previous
#include <cuda_runtime.h>
#include <cuda_bf16.h>
#include <cstdint>

// L1 loss: sum(|out - target|) / N_VEH over N_VEH x N_FEAT fp32.
// Pure HBM-streaming reduction: 536.9 MB read, 4 B written.
//
// R6: deepen per-thread load batch to 8 float4-pairs (16 LDG.128 in flight)
// to cut batch-boundary refill bubbles. ~70 regs -> ~3 CTAs/SM, but in-flight
// bytes/SM (~49KB) still far exceed the ~18KB bandwidth-delay requirement.
// Epilogue: R5's device-global atomicAdd + self-resetting ticket (no memset).

static constexpr int N_FEAT = 8;
static constexpr int BLOCK  = 256;
static constexpr int GRID   = 2048;

__device__ float        g_accum  = 0.0f;
__device__ unsigned int g_ticket = 0;

__global__ __launch_bounds__(BLOCK)
void l1_reduce_kernel(const float4* __restrict__ a,
                      const float4* __restrict__ b,
                      float* __restrict__ res,
                      int n_vec4, float inv_rows)
{
    float acc = 0.0f;
    int stride = GRID * BLOCK;
    int i = blockIdx.x * BLOCK + threadIdx.x;

    // 8 independent float4-pairs per iteration: 16 LDG.128 in flight.
    #pragma unroll 1
    for (; i + 7 * stride < n_vec4; i += 8 * stride) {
        float4 av[8], bv[8];
        #pragma unroll
        for (int k = 0; k < 8; k++) av[k] = __ldcs(&a[i + k * stride]);
        #pragma unroll
        for (int k = 0; k < 8; k++) bv[k] = __ldcs(&b[i + k * stride]);
        #pragma unroll
        for (int k = 0; k < 8; k++) {
            acc += fabsf(av[k].x - bv[k].x) + fabsf(av[k].y - bv[k].y)
                 + fabsf(av[k].z - bv[k].z) + fabsf(av[k].w - bv[k].w);
        }
    }
    // Tail.
    for (; i < n_vec4; i += stride) {
        float4 av = __ldcs(&a[i]);
        float4 bv = __ldcs(&b[i]);
        acc += fabsf(av.x - bv.x) + fabsf(av.y - bv.y) + fabsf(av.z - bv.z) + fabsf(av.w - bv.w);
    }

    // Warp reduce.
    #pragma unroll
    for (int o = 16; o > 0; o >>= 1)
        acc += __shfl_xor_sync(0xFFFFFFFFu, acc, o);

    __shared__ float smem[BLOCK / 32];
    if ((threadIdx.x & 31) == 0)
        smem[threadIdx.x >> 5] = acc;
    __syncthreads();

    if (threadIdx.x == 0) {
        float bsum = 0.0f;
        #pragma unroll
        for (int w = 0; w < BLOCK / 32; w++) bsum += smem[w];

        atomicAdd(&g_accum, bsum);
        __threadfence();
        // atomicInc wraps to 0 when old == GRID-1 -> self-resetting across
        // graph replays. Every block's atomicAdd precedes its atomicInc, so
        // the wrapping thread observes all contributions.
        unsigned int t = atomicInc(&g_ticket, GRID - 1);
        if (t == GRID - 1) {
            __threadfence();
            float tot = *((volatile float*)&g_accum);
            *res = tot * inv_rows;
            g_accum = 0.0f;   // reset for next graph replay
        }
    }
}

extern "C" void kernel_launch(void* const* d_in, const int* in_sizes, int n_in,
                              void* d_out, int out_size)
{
    const float4* a = (const float4*)d_in[0];   // out
    const float4* b = (const float4*)d_in[1];   // target
    float* res = (float*)d_out;

    long long n_elem = (long long)in_sizes[0];  // N_VEH * N_FEAT
    int n_vec4 = (int)(n_elem / 4);
    float inv_rows = (float)((double)N_FEAT / (double)n_elem);

    l1_reduce_kernel<<<GRID, BLOCK>>>(a, b, res, n_vec4, inv_rows);
}

// round 7
// speedup vs baseline: 1.0307x; 1.0060x over previous
#include <cuda_runtime.h>
#include <cuda_bf16.h>
#include <cstdint>

// L1 loss: sum(|out - target|) / N_VEH over N_VEH x N_FEAT fp32.
// Pure HBM-streaming reduction: 536.9 MB read, 4 B written.
//
// R7: single-wave grid. At 38 regs x 256 thr, 6 CTAs/SM are resident, so
// GRID = 148*6 = 888 runs as exactly ONE wave (GRID=2048 ran 2.3 uneven
// waves, paying wave transitions + a partial-wave tail). Inner loop is the
// proven 4-batch (8 LDG.128 in flight); NO launch-bounds reg cap (the R3
// cap destroyed load batching). Epilogue: device-global atomicAdd +
// self-resetting ticket (no memset node).

static constexpr int N_FEAT = 8;
static constexpr int BLOCK  = 256;
static constexpr int GRID   = 148 * 6;   // 888: one full wave at 6 CTAs/SM

__device__ float        g_accum  = 0.0f;
__device__ unsigned int g_ticket = 0;

__global__ __launch_bounds__(BLOCK)
void l1_reduce_kernel(const float4* __restrict__ a,
                      const float4* __restrict__ b,
                      float* __restrict__ res,
                      int n_vec4, float inv_rows)
{
    float acc = 0.0f;
    int stride = GRID * BLOCK;
    int i = blockIdx.x * BLOCK + threadIdx.x;

    // Batch 4 independent float4-pairs per iteration (8 LDG.128 in flight).
    #pragma unroll 1
    for (; i + 3 * stride < n_vec4; i += 4 * stride) {
        float4 a0 = __ldcs(&a[i]);
        float4 a1 = __ldcs(&a[i + stride]);
        float4 a2 = __ldcs(&a[i + 2 * stride]);
        float4 a3 = __ldcs(&a[i + 3 * stride]);
        float4 b0 = __ldcs(&b[i]);
        float4 b1 = __ldcs(&b[i + stride]);
        float4 b2 = __ldcs(&b[i + 2 * stride]);
        float4 b3 = __ldcs(&b[i + 3 * stride]);
        acc += fabsf(a0.x - b0.x) + fabsf(a0.y - b0.y) + fabsf(a0.z - b0.z) + fabsf(a0.w - b0.w);
        acc += fabsf(a1.x - b1.x) + fabsf(a1.y - b1.y) + fabsf(a1.z - b1.z) + fabsf(a1.w - b1.w);
        acc += fabsf(a2.x - b2.x) + fabsf(a2.y - b2.y) + fabsf(a2.z - b2.z) + fabsf(a2.w - b2.w);
        acc += fabsf(a3.x - b3.x) + fabsf(a3.y - b3.y) + fabsf(a3.z - b3.z) + fabsf(a3.w - b3.w);
    }
    // Tail.
    for (; i < n_vec4; i += stride) {
        float4 av = __ldcs(&a[i]);
        float4 bv = __ldcs(&b[i]);
        acc += fabsf(av.x - bv.x) + fabsf(av.y - bv.y) + fabsf(av.z - bv.z) + fabsf(av.w - bv.w);
    }

    // Warp reduce.
    #pragma unroll
    for (int o = 16; o > 0; o >>= 1)
        acc += __shfl_xor_sync(0xFFFFFFFFu, acc, o);

    __shared__ float smem[BLOCK / 32];
    if ((threadIdx.x & 31) == 0)
        smem[threadIdx.x >> 5] = acc;
    __syncthreads();

    if (threadIdx.x == 0) {
        float bsum = 0.0f;
        #pragma unroll
        for (int w = 0; w < BLOCK / 32; w++) bsum += smem[w];

        atomicAdd(&g_accum, bsum);
        __threadfence();
        // atomicInc wraps to 0 when old == GRID-1 -> self-resetting across
        // graph replays. Every block's atomicAdd precedes its atomicInc, so
        // the wrapping thread observes all contributions.
        unsigned int t = atomicInc(&g_ticket, GRID - 1);
        if (t == GRID - 1) {
            __threadfence();
            float tot = *((volatile float*)&g_accum);
            *res = tot * inv_rows;
            g_accum = 0.0f;   // reset for next graph replay
        }
    }
}

extern "C" void kernel_launch(void* const* d_in, const int* in_sizes, int n_in,
                              void* d_out, int out_size)
{
    const float4* a = (const float4*)d_in[0];   // out
    const float4* b = (const float4*)d_in[1];   // target
    float* res = (float*)d_out;

    long long n_elem = (long long)in_sizes[0];  // N_VEH * N_FEAT
    int n_vec4 = (int)(n_elem / 4);
    float inv_rows = (float)((double)N_FEAT / (double)n_elem);

    l1_reduce_kernel<<<GRID, BLOCK>>>(a, b, res, n_vec4, inv_rows);
}

// round 8
// speedup vs baseline: 1.0394x; 1.0085x over previous
#include <cuda_runtime.h>
#include <cuda_bf16.h>
#include <cstdint>

// L1 loss: sum(|out - target|) / N_VEH over N_VEH x N_FEAT fp32.
// Pure HBM-streaming reduction: 536.9 MB read, 4 B written.
//
// R8 = R7 (single-wave, 888 CTAs, 4-batch LDG.128 loop, device-global
// atomicAdd + self-resetting ticket epilogue, no memset node) + split
// accumulator chains (acc0/acc1) to halve the 16-FADD serial dependency
// between load batches. At 6.66 TB/s we are at the path-independent LTS
// cap (~6300 B/cyc); this round is ceiling confirmation.

static constexpr int N_FEAT = 8;
static constexpr int BLOCK  = 256;
static constexpr int GRID   = 148 * 6;   // 888: one full wave at 6 CTAs/SM

__device__ float        g_accum  = 0.0f;
__device__ unsigned int g_ticket = 0;

__global__ __launch_bounds__(BLOCK)
void l1_reduce_kernel(const float4* __restrict__ a,
                      const float4* __restrict__ b,
                      float* __restrict__ res,
                      int n_vec4, float inv_rows)
{
    float acc0 = 0.0f, acc1 = 0.0f;
    int stride = GRID * BLOCK;
    int i = blockIdx.x * BLOCK + threadIdx.x;

    // Batch 4 independent float4-pairs per iteration (8 LDG.128 in flight);
    // two independent accumulation chains.
    #pragma unroll 1
    for (; i + 3 * stride < n_vec4; i += 4 * stride) {
        float4 a0 = __ldcs(&a[i]);
        float4 a1 = __ldcs(&a[i + stride]);
        float4 a2 = __ldcs(&a[i + 2 * stride]);
        float4 a3 = __ldcs(&a[i + 3 * stride]);
        float4 b0 = __ldcs(&b[i]);
        float4 b1 = __ldcs(&b[i + stride]);
        float4 b2 = __ldcs(&b[i + 2 * stride]);
        float4 b3 = __ldcs(&b[i + 3 * stride]);
        acc0 += fabsf(a0.x - b0.x) + fabsf(a0.y - b0.y) + fabsf(a0.z - b0.z) + fabsf(a0.w - b0.w);
        acc1 += fabsf(a1.x - b1.x) + fabsf(a1.y - b1.y) + fabsf(a1.z - b1.z) + fabsf(a1.w - b1.w);
        acc0 += fabsf(a2.x - b2.x) + fabsf(a2.y - b2.y) + fabsf(a2.z - b2.z) + fabsf(a2.w - b2.w);
        acc1 += fabsf(a3.x - b3.x) + fabsf(a3.y - b3.y) + fabsf(a3.z - b3.z) + fabsf(a3.w - b3.w);
    }
    // Tail.
    for (; i < n_vec4; i += stride) {
        float4 av = __ldcs(&a[i]);
        float4 bv = __ldcs(&b[i]);
        acc0 += fabsf(av.x - bv.x) + fabsf(av.y - bv.y) + fabsf(av.z - bv.z) + fabsf(av.w - bv.w);
    }
    float acc = acc0 + acc1;

    // Warp reduce.
    #pragma unroll
    for (int o = 16; o > 0; o >>= 1)
        acc += __shfl_xor_sync(0xFFFFFFFFu, acc, o);

    __shared__ float smem[BLOCK / 32];
    if ((threadIdx.x & 31) == 0)
        smem[threadIdx.x >> 5] = acc;
    __syncthreads();

    if (threadIdx.x == 0) {
        float bsum = 0.0f;
        #pragma unroll
        for (int w = 0; w < BLOCK / 32; w++) bsum += smem[w];

        atomicAdd(&g_accum, bsum);
        __threadfence();
        // atomicInc wraps to 0 when old == GRID-1 -> self-resetting across
        // graph replays. Every block's atomicAdd precedes its atomicInc, so
        // the wrapping thread observes all contributions.
        unsigned int t = atomicInc(&g_ticket, GRID - 1);
        if (t == GRID - 1) {
            __threadfence();
            float tot = *((volatile float*)&g_accum);
            *res = tot * inv_rows;
            g_accum = 0.0f;   // reset for next graph replay
        }
    }
}

extern "C" void kernel_launch(void* const* d_in, const int* in_sizes, int n_in,
                              void* d_out, int out_size)
{
    const float4* a = (const float4*)d_in[0];   // out
    const float4* b = (const float4*)d_in[1];   // target
    float* res = (float*)d_out;

    long long n_elem = (long long)in_sizes[0];  // N_VEH * N_FEAT
    int n_vec4 = (int)(n_elem / 4);
    float inv_rows = (float)((double)N_FEAT / (double)n_elem);

    l1_reduce_kernel<<<GRID, BLOCK>>>(a, b, res, n_vec4, inv_rows);
}